// round 9
// baseline (speedup 1.0000x reference)
#include <cuda_runtime.h>
#include <cuda_bf16.h>
#include <cstdint>

#define NN   100000
#define EE   1600000
#define FIN  256
#define HID  128
#define NC   16
#define NB_SCAN ((NN + 1023) / 1024)

// ---------------- scratch ----------------------------------------------------
static __device__ float g_h[(size_t)NN * HID];     // h' = (x@W1) * dinv[row]
static __device__ float g_z[(size_t)NN * NC];      // z' = (relu(...)@W2)*dinv
static __device__ float g_dinv[NN];
static __device__ int   g_deg[NN];
static __device__ int   g_rowptr[NN + 1];
static __device__ int   g_cursor[NN];
static __device__ int   g_adj[EE];                 // src ids grouped by dst
static __device__ int   g_bsum[NB_SCAN];

// ---------------- degree / normalization ------------------------------------
__global__ void k_deg_init() {
    int i = blockIdx.x * blockDim.x + threadIdx.x;
    if (i < NN) g_deg[i] = 1;   // self loop
}
__global__ void k_deg_count(const int* __restrict__ dst) {
    int e = blockIdx.x * blockDim.x + threadIdx.x;
    if (e < EE) atomicAdd(&g_deg[dst[e]], 1);
}
__global__ void k_dinv() {
    int i = blockIdx.x * blockDim.x + threadIdx.x;
    if (i < NN) g_dinv[i] = rsqrtf((float)g_deg[i]);
}

// ---------------- CSR build ----------------------------------------------------
__global__ __launch_bounds__(256) void k_scan_block() {
    __shared__ int sS[256];
    const int t = threadIdx.x;
    const int base = blockIdx.x * 1024 + t * 4;
    int v[4], s = 0;
    #pragma unroll
    for (int q = 0; q < 4; q++) {
        int i = base + q;
        v[q] = (i < NN) ? (g_deg[i] - 1) : 0;
        s += v[q];
    }
    sS[t] = s;
    __syncthreads();
    #pragma unroll
    for (int off = 1; off < 256; off <<= 1) {
        int x = (t >= off) ? sS[t - off] : 0;
        __syncthreads();
        sS[t] += x;
        __syncthreads();
    }
    if (t == 255) g_bsum[blockIdx.x] = sS[255];
    int run = sS[t] - s;
    #pragma unroll
    for (int q = 0; q < 4; q++) {
        int i = base + q;
        if (i < NN) g_rowptr[i] = run;
        run += v[q];
    }
}
// parallel scan over the 98 block sums (was a serial 1-thread loop)
__global__ void k_scan_top() {
    __shared__ int sS[128];
    const int t = threadIdx.x;
    int v = (t < NB_SCAN) ? g_bsum[t] : 0;
    sS[t] = v;
    __syncthreads();
    #pragma unroll
    for (int off = 1; off < 128; off <<= 1) {
        int x = (t >= off) ? sS[t - off] : 0;
        __syncthreads();
        sS[t] += x;
        __syncthreads();
    }
    if (t < NB_SCAN) g_bsum[t] = sS[t] - v;   // exclusive prefix
}
__global__ void k_scan_add() {
    int i = blockIdx.x * blockDim.x + threadIdx.x;
    if (i < NN) {
        int r = g_rowptr[i] + g_bsum[i >> 10];
        g_rowptr[i] = r;
        g_cursor[i] = r;
    }
    if (i == 0) g_rowptr[NN] = EE;
}
__global__ void k_fill(const int* __restrict__ src, const int* __restrict__ dst) {
    int e = blockIdx.x * blockDim.x + threadIdx.x;
    if (e < EE) {
        int d = dst[e];
        int pos = atomicAdd(&g_cursor[d], 1);
        g_adj[pos] = src[e];
    }
}

// ---------------- bf16 split helpers -----------------------------------------
__device__ __forceinline__ uint32_t pack_bf16x2(float k1, float k0) {
    uint32_t r;
    asm("cvt.rn.bf16x2.f32 %0, %1, %2;" : "=r"(r) : "f"(k1), "f"(k0));
    return r;
}
__device__ __forceinline__ float bf_lo(uint32_t u) { return __uint_as_float(u << 16); }
__device__ __forceinline__ float bf_hi(uint32_t u) { return __uint_as_float(u & 0xFFFF0000u); }

__device__ __forceinline__ void mma_bf16(float* d, const uint32_t* a, const uint32_t* b) {
    asm volatile(
        "mma.sync.aligned.m16n8k16.row.col.f32.bf16.bf16.f32 "
        "{%0,%1,%2,%3}, {%4,%5,%6,%7}, {%8,%9}, {%0,%1,%2,%3};"
        : "+f"(d[0]), "+f"(d[1]), "+f"(d[2]), "+f"(d[3])
        : "r"(a[0]), "r"(a[1]), "r"(a[2]), "r"(a[3]), "r"(b[0]), "r"(b[1]));
}

// ---------------- GEMM1: g_h = (x[N,256] @ W1[256,128]) * dinv ---------------
// 128x128 tile, BK=32, 8 warps (2Mx4N, warp tile 64x32). 3xBF16 split
// (ah*bh + al*bh + ah*bl), split ONCE at staging, conflict-free [row][kpair]
// smem with pad 20. Single buffer + register prefetch; 2 CTAs/SM.
#define PAD 20
__global__ __launch_bounds__(256, 2) void k_gemm1(const float* __restrict__ A,
                                                  const float* __restrict__ B) {
    __shared__ uint32_t As_h[128][PAD];
    __shared__ uint32_t As_l[128][PAD];
    __shared__ uint32_t Bs_h[128][PAD];
    __shared__ uint32_t Bs_l[128][PAD];

    const int tid  = threadIdx.x;
    const int warp = tid >> 5, lane = tid & 31;
    const int blockM = blockIdx.x * 128;
    const int wm = (warp >> 2) * 64;   // 0 / 64
    const int wn = (warp & 3) * 32;    // 0..96
    const int fr  = lane >> 2;
    const int fkp = lane & 3;

    float acc[4][4][4];
    #pragma unroll
    for (int i = 0; i < 4; i++)
        #pragma unroll
        for (int j = 0; j < 4; j++)
            #pragma unroll
            for (int q = 0; q < 4; q++) acc[i][j][q] = 0.f;

    const int aR = tid >> 1;             // A row 0..127
    const int aH = tid & 1;              // k half: 0 -> k 0..15, 1 -> k 16..31
    const int bC = tid & 127;            // B col 0..127
    const int bH = tid >> 7;             // k half

    float4 av[4];
    float  bv[16];

    auto loadRegs = [&](int k0) {
        const float* arow = &A[(size_t)(blockM + aR) * FIN + k0 + aH * 16];
        bool ok = (blockM + aR) < NN;
        #pragma unroll
        for (int q = 0; q < 4; q++)
            av[q] = ok ? *(const float4*)&arow[q * 4] : make_float4(0.f,0.f,0.f,0.f);
        #pragma unroll
        for (int q = 0; q < 16; q++)
            bv[q] = B[(size_t)(k0 + bH * 16 + q) * HID + bC];
    };
    auto packStore = [&]() {
        uint32_t h[8], l[8];
        float af[16] = {av[0].x,av[0].y,av[0].z,av[0].w, av[1].x,av[1].y,av[1].z,av[1].w,
                        av[2].x,av[2].y,av[2].z,av[2].w, av[3].x,av[3].y,av[3].z,av[3].w};
        #pragma unroll
        for (int j = 0; j < 8; j++) {
            h[j] = pack_bf16x2(af[2*j+1], af[2*j]);
            l[j] = pack_bf16x2(af[2*j+1] - bf_hi(h[j]), af[2*j] - bf_lo(h[j]));
        }
        *(uint4*)&As_h[aR][aH * 8]     = make_uint4(h[0],h[1],h[2],h[3]);
        *(uint4*)&As_h[aR][aH * 8 + 4] = make_uint4(h[4],h[5],h[6],h[7]);
        *(uint4*)&As_l[aR][aH * 8]     = make_uint4(l[0],l[1],l[2],l[3]);
        *(uint4*)&As_l[aR][aH * 8 + 4] = make_uint4(l[4],l[5],l[6],l[7]);
        #pragma unroll
        for (int j = 0; j < 8; j++) {
            h[j] = pack_bf16x2(bv[2*j+1], bv[2*j]);
            l[j] = pack_bf16x2(bv[2*j+1] - bf_hi(h[j]), bv[2*j] - bf_lo(h[j]));
        }
        *(uint4*)&Bs_h[bC][bH * 8]     = make_uint4(h[0],h[1],h[2],h[3]);
        *(uint4*)&Bs_h[bC][bH * 8 + 4] = make_uint4(h[4],h[5],h[6],h[7]);
        *(uint4*)&Bs_l[bC][bH * 8]     = make_uint4(l[0],l[1],l[2],l[3]);
        *(uint4*)&Bs_l[bC][bH * 8 + 4] = make_uint4(l[4],l[5],l[6],l[7]);
    };

    loadRegs(0);
    for (int ch = 0; ch < 8; ch++) {
        packStore();
        __syncthreads();
        if (ch < 7) loadRegs((ch + 1) * 32);

        #pragma unroll
        for (int kb = 0; kb < 16; kb += 8) {
            uint32_t ah[4][4], bh[4][2];
            #pragma unroll
            for (int mt = 0; mt < 4; mt++) {
                int r = wm + mt * 16 + fr;
                ah[mt][0] = As_h[r][kb + fkp];
                ah[mt][1] = As_h[r + 8][kb + fkp];
                ah[mt][2] = As_h[r][kb + fkp + 4];
                ah[mt][3] = As_h[r + 8][kb + fkp + 4];
            }
            #pragma unroll
            for (int nt = 0; nt < 4; nt++) {
                int c = wn + nt * 8 + fr;
                bh[nt][0] = Bs_h[c][kb + fkp];
                bh[nt][1] = Bs_h[c][kb + fkp + 4];
            }
            #pragma unroll
            for (int mt = 0; mt < 4; mt++)
                #pragma unroll
                for (int nt = 0; nt < 4; nt++)
                    mma_bf16(acc[mt][nt], ah[mt], bh[nt]);
            {   // al * bh
                uint32_t al[4][4];
                #pragma unroll
                for (int mt = 0; mt < 4; mt++) {
                    int r = wm + mt * 16 + fr;
                    al[mt][0] = As_l[r][kb + fkp];
                    al[mt][1] = As_l[r + 8][kb + fkp];
                    al[mt][2] = As_l[r][kb + fkp + 4];
                    al[mt][3] = As_l[r + 8][kb + fkp + 4];
                }
                #pragma unroll
                for (int mt = 0; mt < 4; mt++)
                    #pragma unroll
                    for (int nt = 0; nt < 4; nt++)
                        mma_bf16(acc[mt][nt], al[mt], bh[nt]);
            }
            {   // ah * bl
                uint32_t bl[4][2];
                #pragma unroll
                for (int nt = 0; nt < 4; nt++) {
                    int c = wn + nt * 8 + fr;
                    bl[nt][0] = Bs_l[c][kb + fkp];
                    bl[nt][1] = Bs_l[c][kb + fkp + 4];
                }
                #pragma unroll
                for (int mt = 0; mt < 4; mt++)
                    #pragma unroll
                    for (int nt = 0; nt < 4; nt++)
                        mma_bf16(acc[mt][nt], ah[mt], bl[nt]);
            }
        }
        __syncthreads();
    }

    #pragma unroll
    for (int mt = 0; mt < 4; mt++) {
        #pragma unroll
        for (int half = 0; half < 2; half++) {
            int r = blockM + wm + mt * 16 + fr + half * 8;
            if (r < NN) {
                float di = g_dinv[r];
                #pragma unroll
                for (int nt = 0; nt < 4; nt++) {
                    int c = wn + nt * 8 + 2 * fkp;
                    float2 v = make_float2(acc[mt][nt][half * 2 + 0] * di,
                                           acc[mt][nt][half * 2 + 1] * di);
                    *(float2*)&g_h[(size_t)r * HID + c] = v;
                }
            }
        }
    }
}

// ---------------- fused aggregate-1 + GEMM2 -----------------------------------
// 512 threads, 16 warps: warp w gathers node nb+w (unroll-4 for MLP), then
// threads 0..255 do the dense z' = (relu(sum*di+b1)@W2)*di.
__global__ __launch_bounds__(512) void k_gemm2(const float* __restrict__ b1,
                                               const float* __restrict__ W2) {
    __shared__ float sRow[16][132];
    __shared__ float sW[HID * NC];
    __shared__ float sB1[HID];
    __shared__ float sDi[16];
    const int tid = threadIdx.x;
    const int warp = tid >> 5, lane = tid & 31;
    const int nb = blockIdx.x * 16;

    for (int i = tid; i < HID * NC; i += 512) sW[i] = W2[i];
    if (tid < HID) sB1[tid] = b1[tid];
    if (tid < 16) { int node = nb + tid; sDi[tid] = (node < NN) ? g_dinv[node] : 0.f; }

    {
        int node = nb + warp;
        if (node < NN) {
            float4 a0 = *(const float4*)&g_h[(size_t)node * HID + lane * 4]; // self
            float4 a1 = make_float4(0.f, 0.f, 0.f, 0.f);
            float4 a2 = make_float4(0.f, 0.f, 0.f, 0.f);
            float4 a3 = make_float4(0.f, 0.f, 0.f, 0.f);
            int j   = __ldg(&g_rowptr[node]);
            int end = __ldg(&g_rowptr[node + 1]);
            for (; j + 3 < end; j += 4) {
                int s0 = __ldg(&g_adj[j]);
                int s1 = __ldg(&g_adj[j + 1]);
                int s2 = __ldg(&g_adj[j + 2]);
                int s3 = __ldg(&g_adj[j + 3]);
                float4 v0 = *(const float4*)&g_h[(size_t)s0 * HID + lane * 4];
                float4 v1 = *(const float4*)&g_h[(size_t)s1 * HID + lane * 4];
                float4 v2 = *(const float4*)&g_h[(size_t)s2 * HID + lane * 4];
                float4 v3 = *(const float4*)&g_h[(size_t)s3 * HID + lane * 4];
                a0.x += v0.x; a0.y += v0.y; a0.z += v0.z; a0.w += v0.w;
                a1.x += v1.x; a1.y += v1.y; a1.z += v1.z; a1.w += v1.w;
                a2.x += v2.x; a2.y += v2.y; a2.z += v2.z; a2.w += v2.w;
                a3.x += v3.x; a3.y += v3.y; a3.z += v3.z; a3.w += v3.w;
            }
            for (; j < end; j++) {
                int s0 = __ldg(&g_adj[j]);
                float4 v0 = *(const float4*)&g_h[(size_t)s0 * HID + lane * 4];
                a0.x += v0.x; a0.y += v0.y; a0.z += v0.z; a0.w += v0.w;
            }
            a0.x += a1.x + a2.x + a3.x;
            a0.y += a1.y + a2.y + a3.y;
            a0.z += a1.z + a2.z + a3.z;
            a0.w += a1.w + a2.w + a3.w;
            *(float4*)&sRow[warp][lane * 4] = a0;
        }
    }
    __syncthreads();

    if (tid < 256) {
        int ln = tid >> 4, c = tid & 15;
        int node = nb + ln;
        if (node < NN) {
            float di = sDi[ln];
            float acc = 0.f;
            #pragma unroll
            for (int k = 0; k < HID; k++) {
                float a = fmaf(sRow[ln][k], di, sB1[k]);
                a = fmaxf(a, 0.f);
                acc = fmaf(a, sW[k * NC + c], acc);
            }
            g_z[(size_t)node * NC + c] = acc * di;
        }
    }
}

// ---------------- aggregate layer 2 (CSR, unroll-4) + final bias --------------
__global__ __launch_bounds__(256) void k_agg2(const float* __restrict__ b2,
                                              float* __restrict__ out) {
    int gid = blockIdx.x * blockDim.x + threadIdx.x;
    int node = gid >> 4;
    if (node >= NN) return;
    int c = gid & 15;

    float a0 = g_z[(size_t)node * NC + c];   // self
    float a1 = 0.f, a2 = 0.f, a3 = 0.f;
    int j   = __ldg(&g_rowptr[node]);
    int end = __ldg(&g_rowptr[node + 1]);
    for (; j + 3 < end; j += 4) {
        int s0 = __ldg(&g_adj[j]);
        int s1 = __ldg(&g_adj[j + 1]);
        int s2 = __ldg(&g_adj[j + 2]);
        int s3 = __ldg(&g_adj[j + 3]);
        a0 += g_z[(size_t)s0 * NC + c];
        a1 += g_z[(size_t)s1 * NC + c];
        a2 += g_z[(size_t)s2 * NC + c];
        a3 += g_z[(size_t)s3 * NC + c];
    }
    for (; j < end; j++) {
        int s0 = __ldg(&g_adj[j]);
        a0 += g_z[(size_t)s0 * NC + c];
    }
    a0 += a1 + a2 + a3;
    out[(size_t)node * NC + c] = fmaf(a0, g_dinv[node], b2[c]);
}

// ---------------- launch -----------------------------------------------------
extern "C" void kernel_launch(void* const* d_in, const int* in_sizes, int n_in,
                              void* d_out, int out_size) {
    const float* x  = (const float*)d_in[0];
    const int*   ei = (const int*)d_in[1];
    const float* W1 = (const float*)d_in[2];
    const float* b1 = (const float*)d_in[3];
    const float* W2 = (const float*)d_in[4];
    const float* b2 = (const float*)d_in[5];
    float* out = (float*)d_out;

    const int* src = ei;        // edge_index[0]
    const int* dst = ei + EE;   // edge_index[1]

    k_deg_init<<<(NN + 255) / 256, 256>>>();
    k_deg_count<<<(EE + 255) / 256, 256>>>(dst);
    k_dinv<<<(NN + 255) / 256, 256>>>();

    // gemm1 only needs dinv -> launch index 3 (ncu capture slot)
    k_gemm1<<<(NN + 127) / 128, 256>>>(x, W1);        // h' = (x@W1)*dinv

    // CSR build
    k_scan_block<<<NB_SCAN, 256>>>();
    k_scan_top<<<1, 128>>>();
    k_scan_add<<<(NN + 255) / 256, 256>>>();
    k_fill<<<(EE + 255) / 256, 256>>>(src, dst);

    k_gemm2<<<(NN + 15) / 16, 512>>>(b1, W2);         // gather + dense -> z'

    k_agg2<<<(NN * 16 + 255) / 256, 256>>>(b2, out);  // gather + bias -> out
}